// round 11
// baseline (speedup 1.0000x reference)
#include <cuda_runtime.h>
#include <math.h>

typedef unsigned long long ull;
#define FULLMASK 0xffffffffu

#define NSEL_BLK  384               // 192 groups x 2 blocks
#define GRID_ALL  592               // one wave: 148 SMs x 4 blocks
#define HSZ       1024
#define HMASK     1023

// dense float4 index space: p0 [0,409600) p1 [409600,512000) p2 [512000,537600)
#define F4_P0   409600
#define F4_P1   512000
#define F4_TOT  537600
#define UNIT    448                 // 1200 weighted units * 448 = 537600

// ---------------- device scratch ----------------
struct SelR {
    int   idx[10];
    int   np;
    float biou, cxg, cyg, twt, tht, f0, f1;
};
__device__ SelR     g_sel[192 * 40];
__device__ unsigned g_gcnt[192];     // per-group arrival counters (self-resetting)
__device__ float    g_part[GRID_ALL];
__device__ unsigned g_count = 0;

struct SmS {
    int      hkey[HSZ], hval[HSZ], hent[HSZ];
    int      e_cell[400];
    unsigned e_obj[400];
    float    e_b0[400], e_b1[400], e_b2[400], e_b3[400], e_f0[400], e_f1[400];
    SelR     sel[40];
    float    red[8];
    int      wcnt[8], wbase[8];
    int      nE;
    int      flag;
};

// ---------------- fast math helpers ----------------
static __device__ __forceinline__ float fsig(float x) {
    return __fdividef(1.0f, 1.0f + __expf(-x));
}
static __device__ __forceinline__ float fsoftplus(float x) {
    return fmaxf(x, 0.0f) + __logf(1.0f + __expf(-fabsf(x)));
}
static __device__ __forceinline__ float ffocal0(float x) {
    float t  = __expf(-fabsf(x));
    float r  = __fdividef(1.0f, 1.0f + t);
    float sg = (x >= 0.0f) ? r : t * r;        // sigmoid(x)
    float ce = fmaxf(x, 0.0f) + __logf(1.0f + t);
    return 0.75f * sg * sg * ce;
}
static __device__ __forceinline__ float ffocal(float x, float z) {
    float t    = __expf(-fabsf(x));
    float r    = __fdividef(1.0f, 1.0f + t);
    float prob = (x >= 0.0f) ? r : t * r;
    float ce   = fmaxf(x, 0.0f) - x * z + __logf(1.0f + t);
    float pt   = prob * z + (1.0f - prob) * (1.0f - z);
    float at   = 0.25f * z + 0.75f * (1.0f - z);
    float om   = 1.0f - pt;
    return at * om * om * ce;
}
static __device__ __forceinline__ unsigned ford(float f) {
    unsigned u = __float_as_uint(f);
    return (u & 0x80000000u) ? ~u : (u | 0x80000000u);
}

static __device__ __forceinline__ float iou_xy(
    const float* __restrict__ predb, int HW, int cell, float gx, float gy, float s,
    float gtx1, float gty1, float gtx2, float gty2, float garea)
{
    float q1 = __ldg(predb + HW + cell);
    float q2 = __ldg(predb + 2 * HW + cell);
    float q3 = __ldg(predb + 3 * HW + cell);
    float q4 = __ldg(predb + 4 * HW + cell);
    float pcx = (fsig(q1) + gx) * s;
    float pcy = (fsig(q2) + gy) * s;
    float pw  = __expf(fminf(fmaxf(q3, -5.0f), 5.0f)) * s;
    float ph  = __expf(fminf(fmaxf(q4, -5.0f), 5.0f)) * s;
    float px1 = pcx - pw * 0.5f, py1 = pcy - ph * 0.5f;
    float px2 = pcx + pw * 0.5f, py2 = pcy + ph * 0.5f;
    float iw    = fmaxf(fminf(px2, gtx2) - fmaxf(px1, gtx1), 0.0f);
    float ih    = fmaxf(fminf(py2, gty2) - fmaxf(py1, gty1), 0.0f);
    float inter = iw * ih;
    float pa    = (px2 - px1) * (py2 - py1);
    return __fdividef(inter, pa + garea - inter + 1e-7f);
}

// deterministic 8-warp block reduction; result valid in warp 0.
static __device__ __forceinline__ float blk_reduce(float v, float* red, int tid) {
    #pragma unroll
    for (int o = 16; o; o >>= 1) v += __shfl_xor_sync(FULLMASK, v, o);
    if ((tid & 31) == 0) red[tid >> 5] = v;
    __syncthreads();
    float r = 0.0f;
    if (tid < 32) {
        r = (tid < 8) ? red[tid] : 0.0f;
        #pragma unroll
        for (int o = 4; o; o >>= 1) r += __shfl_xor_sync(FULLMASK, r, o);
    }
    __syncthreads();
    return r;
}

// dense focal-base over float4 range [lo, hi) of the unified index space
static __device__ __forceinline__ float dense_range(
    int lo, int hi, int tid,
    const float4* v0, const float4* v1, const float4* v2)
{
    float acc = 0.0f;
    // p0 segment
    int a = lo, bnd = hi < F4_P0 ? hi : F4_P0;
    for (int i = a + tid; i < bnd; i += 256) {
        int b = i / 6400, j = i - b * 6400;
        float4 x = __ldg(v0 + (size_t)b * 7 * 6400 + j);
        acc += (ffocal0(x.x) + ffocal0(x.y) + ffocal0(x.z) + ffocal0(x.w))
               * (1.0f / 25600.0f);
    }
    // p1 segment
    a = lo > F4_P0 ? lo : F4_P0; bnd = hi < F4_P1 ? hi : F4_P1;
    for (int i = a + tid; i < bnd; i += 256) {
        int li = i - F4_P0;
        int b = li / 1600, j = li - b * 1600;
        float4 x = __ldg(v1 + (size_t)b * 7 * 1600 + j);
        acc += (ffocal0(x.x) + ffocal0(x.y) + ffocal0(x.z) + ffocal0(x.w))
               * (1.0f / 6400.0f);
    }
    // p2 segment
    a = lo > F4_P1 ? lo : F4_P1; bnd = hi;
    for (int i = a + tid; i < bnd; i += 256) {
        int li = i - F4_P1;
        int b = li / 400, j = li - b * 400;
        float4 x = __ldg(v2 + (size_t)b * 7 * 400 + j);
        acc += (ffocal0(x.x) + ffocal0(x.y) + ffocal0(x.z) + ffocal0(x.w))
               * (1.0f / 1600.0f);
    }
    return acc;
}

// ---------------- the single kernel ----------------
__global__ void __launch_bounds__(256)
k_all(const float* __restrict__ p0, const float* __restrict__ p1,
      const float* __restrict__ p2, const float* __restrict__ tgt,
      float* __restrict__ out)
{
    extern __shared__ char smraw[];
    SmS& sm = *reinterpret_cast<SmS*>(smraw);
    int tid = threadIdx.x, lane = tid & 31, warp = tid >> 5;
    float part = 0.0f;

    // static balanced dense slice for THIS block (weights: sub0=1, sub1=2, dense=3)
    int units_lo, wgt;
    if (blockIdx.x < NSEL_BLK) {
        int grp = blockIdx.x >> 1, sub = blockIdx.x & 1;
        units_lo = grp * 3 + (sub ? 1 : 0);
        wgt      = sub ? 2 : 1;
    } else {
        units_lo = 576 + (blockIdx.x - NSEL_BLK) * 3;
        wgt      = 3;
    }
    int dlo = units_lo * UNIT, dhi = dlo + wgt * UNIT;

    if (blockIdx.x < NSEL_BLK) {
        // ================= selection: warp-global wg handles GTs wg, wg+16, wg+32 ==
        int grp = blockIdx.x >> 1, sub = blockIdx.x & 1;   // grp = lvl*64 + b
        int b = grp & 63, lvl = grp >> 6;
        const float* pred; int Wd, HW; float s;
        if (lvl == 0)      { pred = p0; Wd = 160; HW = 25600; s = (float)(8.0  / 1280.0); }
        else if (lvl == 1) { pred = p1; Wd = 80;  HW = 6400;  s = (float)(16.0 / 1280.0); }
        else               { pred = p2; Wd = 40;  HW = 1600;  s = (float)(32.0 / 1280.0); }
        const float* predb = pred + (size_t)b * 7 * HW;

        int wg0 = sub * 8 + warp;                          // 0..15
        for (int g = wg0; g < 40; g += 16) {
            int gw = grp * 40 + g;
            const float* T = tgt + (size_t)(b * 40 + g) * 7;
            float cls = __ldg(T + 0), cx = __ldg(T + 1), cy = __ldg(T + 2);
            float w   = __ldg(T + 3), h  = __ldg(T + 4);
            float size = fmaxf(w, h) * 1280.0f;
            bool smask = (lvl == 0) ? (size < 128.0f)
                       : (lvl == 1) ? (size >= 48.0f && size < 288.0f)
                                    : (size >= 128.0f);
            if (!(cls == 0.0f && smask)) {                 // invalid GT: no-op
                if (lane == 0) g_sel[gw].np = 0;
                continue;
            }
            float cxg = cx / s, cyg = cy / s;
            float gtx1 = cx - w * 0.5f, gty1 = cy - h * 0.5f;
            float gtx2 = cx + w * 0.5f, gty2 = cy + h * 0.5f;
            float bxlo = gtx1 / s, bxhi = gtx2 / s, bylo = gty1 / s, byhi = gty2 / s;
            float garea = (gtx2 - gtx1) * (gty2 - gty1);

            int x0 = max(0, (int)floorf(fminf(cxg - 2.5f, bxlo)));
            int x1 = min(Wd - 1, (int)ceilf(fmaxf(cxg + 2.5f, bxhi)));
            int y0 = max(0, (int)floorf(fminf(cyg - 2.5f, bylo)));
            int y1 = min(Wd - 1, (int)ceilf(fmaxf(cyg + 2.5f, byhi)));
            int nx  = x1 - x0 + 1;
            int tot = nx * (y1 - y0 + 1);

            int xi = lane % nx, yi = lane / nx;
            int stepy = 32 / nx, stepx = 32 % nx;
            int niter = (lane < tot) ? ((tot - 1 - lane) >> 5) + 1 : 0;

            ull a[10];
            #pragma unroll
            for (int j = 0; j < 10; ++j) a[j] = ~0ull;
            int cnt = 0; float isum = 0.0f;

            for (int it = 0; it < niter; ++it) {
                int x = x0 + xi, y = y0 + yi;
                xi += stepx; yi += stepy;
                if (xi >= nx) { xi -= nx; yi += 1; }

                float gx = (float)x, gy = (float)y;
                bool inc = (fabsf(gx - cxg) < 2.5f) & (fabsf(gy - cyg) < 2.5f);
                bool inb = (gx >= bxlo) & (gx < bxhi) & (gy >= bylo) & (gy < byhi);
                if (!(inc | inb)) continue;
                int cell = y * Wd + x;
                float iou  = iou_xy(predb, HW, cell, gx, gy, s,
                                    gtx1, gty1, gtx2, gty2, garea);
                float q0   = __ldg(predb + cell);
                float cost = fsoftplus(-q0) - 3.0f * __logf(iou + 1e-7f);
                cnt++; isum += iou;
                ull key = ((ull)ford(cost) << 32) | (unsigned)cell;
                if (key < a[9]) {
                    a[9] = key;
                    #pragma unroll
                    for (int j = 8; j >= 0; --j) {
                        ull lo = a[j] < a[j + 1] ? a[j] : a[j + 1];
                        ull hi = a[j] < a[j + 1] ? a[j + 1] : a[j];
                        a[j] = lo; a[j + 1] = hi;
                    }
                }
            }
            #pragma unroll
            for (int o = 16; o; o >>= 1) {
                cnt  += __shfl_xor_sync(FULLMASK, cnt, o);
                isum += __shfl_xor_sync(FULLMASK, isum, o);
            }

            int bc0 = -1;
            #pragma unroll
            for (int t = 0; t < 10; ++t) {
                ull m = a[0];
                #pragma unroll
                for (int o = 16; o; o >>= 1) {
                    ull u = __shfl_xor_sync(FULLMASK, m, o);
                    m = u < m ? u : m;
                }
                int cellv = (m == ~0ull) ? -1 : (int)(unsigned)(m & 0xffffffffu);
                if (t == 0) bc0 = cellv;
                if (lane == 0) g_sel[gw].idx[t] = cellv;
                if (a[0] == m && m != ~0ull) {
                    #pragma unroll
                    for (int j = 0; j < 9; ++j) a[j] = a[j + 1];
                    a[9] = ~0ull;
                }
            }
            if (lane == 0) {
                if (cnt > 0) {
                    int bx = bc0 % Wd, by = bc0 / Wd;
                    float biou = iou_xy(predb, HW, bc0, (float)bx, (float)by, s,
                                        gtx1, gty1, gtx2, gty2, garea);
                    int hi = cnt < 10 ? cnt : 10;
                    int np = (int)floorf(isum);
                    np = np < 1 ? 1 : np;
                    np = np > hi ? hi : np;
                    SelR& sr = g_sel[gw];
                    sr.np = np;   sr.biou = biou;
                    sr.cxg = cxg; sr.cyg = cyg;
                    sr.twt = __logf(w / s + 1e-7f);
                    sr.tht = __logf(h / s + 1e-7f);
                    sr.f0  = __ldg(T + 5); sr.f1 = __ldg(T + 6);
                } else {
                    g_sel[gw].np = 0;
                }
            }
        }

        // ---- group arrival: last of 2 blocks performs apply + loss ----
        __syncthreads();
        if (tid == 0) {
            __threadfence();
            unsigned t = atomicAdd(&g_gcnt[grp], 1u);
            sm.flag = (t == 1u) ? 1 : 0;
        }
        __syncthreads();

        if (sm.flag) {
            if (tid == 0) g_gcnt[grp] = 0;                 // reset for next replay
            __threadfence();                               // acquire g_sel writes
            float invHW = 1.0f / (float)HW;

            {
                const int* src = (const int*)&g_sel[grp * 40];
                int*       dst = (int*)sm.sel;
                for (int i = tid; i < 40 * (int)(sizeof(SelR) / 4); i += 256)
                    dst[i] = src[i];
            }
            for (int i = tid; i < HSZ; i += 256) { sm.hkey[i] = -1; sm.hval[i] = -1; }
            __syncthreads();

            // phase A: ownership (owner = max g per cell) via shared hash
            for (int i = tid; i < 400; i += 256) {
                int g2 = i / 10, k = i % 10;
                if (k < sm.sel[g2].np) {
                    int cell = sm.sel[g2].idx[k];
                    int slot = (int)(((unsigned)cell * 2654435761u) >> 22) & HMASK;
                    while (true) {
                        int kk = atomicCAS(&sm.hkey[slot], -1, cell);
                        if (kk == -1 || kk == cell) break;
                        slot = (slot + 1) & HMASK;
                    }
                    atomicMax(&sm.hval[slot], g2);
                }
            }
            __syncthreads();

            // phase B: deterministic entry assignment (tid-ordered ballot)
            int base = 0;
            #pragma unroll
            for (int it = 0; it < 2; ++it) {
                int i = it * 256 + tid;
                int g2 = i / 10, k = i % 10;
                bool act = (i < 400) && (k < sm.sel[g2].np);
                int slot = -1; bool own = false;
                if (act) {
                    int cell = sm.sel[g2].idx[k];
                    slot = (int)(((unsigned)cell * 2654435761u) >> 22) & HMASK;
                    while (sm.hkey[slot] != cell) slot = (slot + 1) & HMASK;
                    own = (sm.hval[slot] == g2);
                }
                unsigned bal = __ballot_sync(FULLMASK, own);
                int wpre = __popc(bal & ((1u << lane) - 1));
                if (lane == 0) sm.wcnt[warp] = __popc(bal);
                __syncthreads();
                if (tid == 0) {
                    int ssum = base;
                    #pragma unroll
                    for (int w2 = 0; w2 < 8; ++w2) { sm.wbase[w2] = ssum; ssum += sm.wcnt[w2]; }
                    sm.nE = ssum;
                }
                __syncthreads();
                if (own) {
                    int e = sm.wbase[warp] + wpre;
                    const SelR& sr = sm.sel[g2];
                    int cell = sr.idx[k];
                    float gxi = (float)(cell % Wd), gyi = (float)(cell / Wd);
                    sm.e_cell[e] = cell;
                    sm.e_obj[e]  = 0u;
                    sm.e_b0[e] = sr.cxg - gxi;
                    sm.e_b1[e] = sr.cyg - gyi;
                    sm.e_b2[e] = sr.twt;
                    sm.e_b3[e] = sr.tht;
                    sm.e_f0[e] = sr.f0;
                    sm.e_f1[e] = sr.f1;
                    sm.hent[slot] = e;
                }
                base = sm.nE;
                __syncthreads();
            }

            // phase C: obj target = max biou over all selecting GTs
            for (int i = tid; i < 400; i += 256) {
                int g2 = i / 10, k = i % 10;
                if (k < sm.sel[g2].np) {
                    int cell = sm.sel[g2].idx[k];
                    int slot = (int)(((unsigned)cell * 2654435761u) >> 22) & HMASK;
                    while (sm.hkey[slot] != cell) slot = (slot + 1) & HMASK;
                    atomicMax(&sm.e_obj[sm.hent[slot]], __float_as_uint(sm.sel[g2].biou));
                }
            }
            __syncthreads();

            // losses over positive cells
            int nE = sm.nE;
            float npos = fmaxf((float)nE, 1.0f);
            float objc = 0.0f, boxs = 0.0f, fts = 0.0f;
            for (int e = tid; e < nE; e += 256) {
                int cl = sm.e_cell[e];
                float q0 = __ldg(predb + cl);
                float q1 = __ldg(predb + HW + cl);
                float q2 = __ldg(predb + 2 * HW + cl);
                float q3 = __ldg(predb + 3 * HW + cl);
                float q4 = __ldg(predb + 4 * HW + cl);
                float q5 = __ldg(predb + 5 * HW + cl);
                float q6 = __ldg(predb + 6 * HW + cl);

                float z = __uint_as_float(sm.e_obj[e]);
                objc += ffocal(q0, z) - ffocal0(q0);

                float gx = (float)(cl % Wd), gy = (float)(cl / Wd);
                float pcx = (fsig(q1) + gx) * s;
                float pcy = (fsig(q2) + gy) * s;
                float pw  = __expf(fminf(fmaxf(q3, -5.0f), 5.0f)) * s;
                float ph  = __expf(fminf(fmaxf(q4, -5.0f), 5.0f)) * s;
                float tcx = (sm.e_b0[e] + gx) * s;
                float tcy = (sm.e_b1[e] + gy) * s;
                float tw  = __expf(sm.e_b2[e]) * s;
                float th  = __expf(sm.e_b3[e]) * s;

                float px1 = pcx - pw * 0.5f, py1 = pcy - ph * 0.5f;
                float px2 = pcx + pw * 0.5f, py2 = pcy + ph * 0.5f;
                float tx1 = tcx - tw * 0.5f, ty1 = tcy - th * 0.5f;
                float tx2 = tcx + tw * 0.5f, ty2 = tcy + th * 0.5f;
                float iw    = fmaxf(fminf(px2, tx2) - fmaxf(px1, tx1), 0.0f);
                float ih    = fmaxf(fminf(py2, ty2) - fmaxf(py1, ty1), 0.0f);
                float inter = iw * ih;
                float uni   = pw * ph + tw * th - inter + 1e-7f;
                float iou   = __fdividef(inter, uni);
                float rho2  = (pcx - tcx) * (pcx - tcx) + (pcy - tcy) * (pcy - tcy);
                float cw = fmaxf(px2, tx2) - fminf(px1, tx1);
                float ch = fmaxf(py2, ty2) - fminf(py1, ty1);
                float c2 = cw * cw + ch * ch + 1e-7f;
                float dv = atanf(__fdividef(tw, th + 1e-7f)) - atanf(__fdividef(pw, ph + 1e-7f));
                float v  = 0.40528473456935108577f * dv * dv;  // 4/pi^2
                float alpha = __fdividef(v, 1.0f - iou + v + 1e-7f);
                float ciou  = iou - __fdividef(rho2, c2) - alpha * v;
                boxs += 1.0f - ciou;

                float pf0 = fsig(q5), pf1 = fsig(q6);
                float d0 = fabsf(pf0 - sm.e_f0[e]);
                float d1 = fabsf(pf1 - sm.e_f1[e]);
                fts += (d0 < 1.0f ? 0.5f * d0 * d0 : d0 - 0.5f)
                     + (d1 < 1.0f ? 0.5f * d1 * d1 : d1 - 0.5f);
            }

            float tobj = blk_reduce(objc, sm.red, tid);
            float tbox = blk_reduce(boxs, sm.red, tid);
            float tft  = blk_reduce(fts,  sm.red, tid);
            part = tobj * invHW + 5.0f * tbox / npos + 1.0f * tft / npos;
        }
    }

    // ================= dense slice (ALL blocks) =================
    {
        float acc = dense_range(dlo, dhi, tid,
                                (const float4*)p0, (const float4*)p1,
                                (const float4*)p2);
        part += blk_reduce(acc, sm.red, tid);
    }

    // ---- arrival counter; last block does the deterministic final sum ----
    if (tid == 0) {
        g_part[blockIdx.x] = part;
        __threadfence();
        unsigned t = atomicAdd(&g_count, 1u);
        sm.flag = (t == GRID_ALL - 1) ? 1 : 0;
    }
    __syncthreads();
    if (sm.flag) {
        __threadfence();
        float acc = 0.0f;
        for (int i = tid; i < GRID_ALL; i += 256) acc += g_part[i];
        float tot = blk_reduce(acc, sm.red, tid);
        if (tid == 0) {
            out[0] = tot / 64.0f;
            g_count = 0;                  // reset for next graph replay
        }
    }
}

// ---------------- host ----------------
extern "C" void kernel_launch(void* const* d_in, const int* in_sizes, int n_in,
                              void* d_out, int out_size)
{
    const float *p0 = nullptr, *p1 = nullptr, *p2 = nullptr, *tg = nullptr;
    for (int i = 0; i < n_in; ++i) {
        int sz = in_sizes[i];
        if      (sz == 64 * 7 * 160 * 160) p0 = (const float*)d_in[i];
        else if (sz == 64 * 7 * 80 * 80)   p1 = (const float*)d_in[i];
        else if (sz == 64 * 7 * 40 * 40)   p2 = (const float*)d_in[i];
        else if (sz == 64 * 40 * 7)        tg = (const float*)d_in[i];
    }

    cudaFuncSetAttribute(k_all, cudaFuncAttributeMaxDynamicSharedMemorySize,
                         (int)sizeof(SmS));

    k_all<<<GRID_ALL, 256, sizeof(SmS)>>>(p0, p1, p2, tg, (float*)d_out);
}

// round 12
// speedup vs baseline: 1.0481x; 1.0481x over previous
#include <cuda_runtime.h>
#include <math.h>

typedef unsigned long long ull;
#define FULLMASK 0xffffffffu

#define NSEL_BLK  960               // 192 groups x 5 blocks, 1 GT/warp
#define GRID_ALL  1184              // + 224 dense starters = exactly 2 waves (148*4)
#define HSZ       1024
#define HMASK     1023

// dense float4 chunks: 1024 float4 each; segment-aligned
// p0: chunks [0,400)  p1: [400,500)  p2: [500,525)
#define NCHUNK    525
#define LUTN      2048

// ---------------- device scratch ----------------
struct SelR {
    int   idx[10];
    int   np;
    float biou, cxg, cyg, twt, tht, f0, f1;
};
__device__ SelR     g_sel[192 * 40];
__device__ unsigned g_gcnt[192];     // per-group arrival counters (self-resetting)
__device__ float    g_part[GRID_ALL];
__device__ float    g_chunksum[NCHUNK];
__device__ unsigned g_chunk_ctr = 0;
__device__ unsigned g_count = 0;
__device__ float2   g_lut[LUTN];     // (value, delta) piecewise-linear focal0

struct SmS {
    float2   lut[LUTN];              // 16 KB
    int      hkey[HSZ], hval[HSZ], hent[HSZ];
    int      e_cell[400];
    unsigned e_obj[400];
    float    e_b0[400], e_b1[400], e_b2[400], e_b3[400], e_f0[400], e_f1[400];
    SelR     sel[40];
    float    red[8];
    int      wcnt[8], wbase[8];
    int      nE;
    int      flag;
    int      chunkid;
};

// ---------------- fast math helpers ----------------
static __device__ __forceinline__ float fsig(float x) {
    return __fdividef(1.0f, 1.0f + __expf(-x));
}
static __device__ __forceinline__ float fsoftplus(float x) {
    return fmaxf(x, 0.0f) + __logf(1.0f + __expf(-fabsf(x)));
}
// exact (MUFU) focal0: 0.75 * sigmoid(x)^2 * softplus(x)
static __device__ __forceinline__ float ffocal0x(float x) {
    float t  = __expf(-fabsf(x));
    float r  = __fdividef(1.0f, 1.0f + t);
    float sg = (x >= 0.0f) ? r : t * r;
    float ce = fmaxf(x, 0.0f) + __logf(1.0f + t);
    return 0.75f * sg * sg * ce;
}
static __device__ __forceinline__ float ffocal(float x, float z) {
    float t    = __expf(-fabsf(x));
    float r    = __fdividef(1.0f, 1.0f + t);
    float prob = (x >= 0.0f) ? r : t * r;
    float ce   = fmaxf(x, 0.0f) - x * z + __logf(1.0f + t);
    float pt   = prob * z + (1.0f - prob) * (1.0f - z);
    float at   = 0.25f * z + 0.75f * (1.0f - z);
    float om   = 1.0f - pt;
    return at * om * om * ce;
}
// LUT focal0 (0 MUFU): linear interp over [-10,10], exact fallback outside
static __device__ __forceinline__ float lut0(float x, const float2* __restrict__ lut) {
    if (fabsf(x) >= 9.99f) return ffocal0x(x);        // ~never for N(0,1)
    float u  = fmaf(x, 102.4f, 1024.0f);              // (x+10)/Δ, Δ=20/2048
    int   i  = (int)u;
    float fr = u - (float)i;
    float2 e = lut[i];
    return fmaf(e.y, fr, e.x);
}
static __device__ __forceinline__ unsigned ford(float f) {
    unsigned u = __float_as_uint(f);
    return (u & 0x80000000u) ? ~u : (u | 0x80000000u);
}

static __device__ __forceinline__ float iou_xy(
    const float* __restrict__ predb, int HW, int cell, float gx, float gy, float s,
    float gtx1, float gty1, float gtx2, float gty2, float garea)
{
    float q1 = __ldg(predb + HW + cell);
    float q2 = __ldg(predb + 2 * HW + cell);
    float q3 = __ldg(predb + 3 * HW + cell);
    float q4 = __ldg(predb + 4 * HW + cell);
    float pcx = (fsig(q1) + gx) * s;
    float pcy = (fsig(q2) + gy) * s;
    float pw  = __expf(fminf(fmaxf(q3, -5.0f), 5.0f)) * s;
    float ph  = __expf(fminf(fmaxf(q4, -5.0f), 5.0f)) * s;
    float px1 = pcx - pw * 0.5f, py1 = pcy - ph * 0.5f;
    float px2 = pcx + pw * 0.5f, py2 = pcy + ph * 0.5f;
    float iw    = fmaxf(fminf(px2, gtx2) - fmaxf(px1, gtx1), 0.0f);
    float ih    = fmaxf(fminf(py2, gty2) - fmaxf(py1, gty1), 0.0f);
    float inter = iw * ih;
    float pa    = (px2 - px1) * (py2 - py1);
    return __fdividef(inter, pa + garea - inter + 1e-7f);
}

// deterministic 8-warp block reduction; result valid in warp 0.
static __device__ __forceinline__ float blk_reduce(float v, float* red, int tid) {
    #pragma unroll
    for (int o = 16; o; o >>= 1) v += __shfl_xor_sync(FULLMASK, v, o);
    if ((tid & 31) == 0) red[tid >> 5] = v;
    __syncthreads();
    float r = 0.0f;
    if (tid < 32) {
        r = (tid < 8) ? red[tid] : 0.0f;
        #pragma unroll
        for (int o = 4; o; o >>= 1) r += __shfl_xor_sync(FULLMASK, r, o);
    }
    __syncthreads();
    return r;
}

// ---------------- LUT builder (tiny pre-kernel) ----------------
__global__ void k_lut()
{
    int i = blockIdx.x * 256 + threadIdx.x;            // 0..2047
    const float D = 20.0f / 2048.0f;
    float x0 = -10.0f + i * D;
    float v0 = ffocal0x(x0);
    float v1 = ffocal0x(x0 + D);
    g_lut[i] = make_float2(v0, v1 - v0);
}

// dense chunk c (1024 float4), LUT-based; deterministic per-chunk sum
static __device__ __forceinline__ float dense_chunk(
    int c, int tid, const float2* __restrict__ lut,
    const float4* __restrict__ v0, const float4* __restrict__ v1,
    const float4* __restrict__ v2)
{
    float acc = 0.0f;
    int base = c * 1024;
    if (c < 400) {
        #pragma unroll
        for (int k = 0; k < 4; ++k) {
            int i = base + k * 256 + tid;
            int b = i / 6400, j = i - b * 6400;
            float4 x = __ldg(v0 + (size_t)b * 44800 + j);
            acc += (lut0(x.x, lut) + lut0(x.y, lut) + lut0(x.z, lut) + lut0(x.w, lut))
                   * (1.0f / 25600.0f);
        }
    } else if (c < 500) {
        #pragma unroll
        for (int k = 0; k < 4; ++k) {
            int i = base - 409600 + k * 256 + tid;
            int b = i / 1600, j = i - b * 1600;
            float4 x = __ldg(v1 + (size_t)b * 11200 + j);
            acc += (lut0(x.x, lut) + lut0(x.y, lut) + lut0(x.z, lut) + lut0(x.w, lut))
                   * (1.0f / 6400.0f);
        }
    } else {
        #pragma unroll
        for (int k = 0; k < 4; ++k) {
            int i = base - 512000 + k * 256 + tid;
            int b = i / 400, j = i - b * 400;
            float4 x = __ldg(v2 + (size_t)b * 2800 + j);
            acc += (lut0(x.x, lut) + lut0(x.y, lut) + lut0(x.z, lut) + lut0(x.w, lut))
                   * (1.0f / 1600.0f);
        }
    }
    return acc;
}

// ---------------- the main kernel ----------------
__global__ void __launch_bounds__(256)
k_all(const float* __restrict__ p0, const float* __restrict__ p1,
      const float* __restrict__ p2, const float* __restrict__ tgt,
      float* __restrict__ out)
{
    extern __shared__ char smraw[];
    SmS& sm = *reinterpret_cast<SmS*>(smraw);
    int tid = threadIdx.x, lane = tid & 31, warp = tid >> 5;
    float part = 0.0f;

    // copy LUT global -> shared (float4 x 4 per thread)
    {
        const float4* src = (const float4*)g_lut;
        float4*       dst = (float4*)sm.lut;
        #pragma unroll
        for (int k = 0; k < 4; ++k) dst[k * 256 + tid] = src[k * 256 + tid];
    }
    // no sync needed yet for sel path (uses exact math); sync before first LUT use

    if (blockIdx.x < NSEL_BLK) {
        // ================= selection: one warp per GT =================
        int grp = blockIdx.x / 5, sub = blockIdx.x % 5;   // grp = lvl*64 + b
        int b = grp & 63, lvl = grp >> 6;
        const float* pred; int Wd, HW; float s;
        if (lvl == 0)      { pred = p0; Wd = 160; HW = 25600; s = (float)(8.0  / 1280.0); }
        else if (lvl == 1) { pred = p1; Wd = 80;  HW = 6400;  s = (float)(16.0 / 1280.0); }
        else               { pred = p2; Wd = 40;  HW = 1600;  s = (float)(32.0 / 1280.0); }
        const float* predb = pred + (size_t)b * 7 * HW;

        int g  = sub * 8 + warp;                          // this warp's GT, 0..39
        int gw = grp * 40 + g;
        {
            const float* T = tgt + (size_t)(b * 40 + g) * 7;
            float cls = __ldg(T + 0), cx = __ldg(T + 1), cy = __ldg(T + 2);
            float w   = __ldg(T + 3), h  = __ldg(T + 4);
            float size = fmaxf(w, h) * 1280.0f;
            bool smask = (lvl == 0) ? (size < 128.0f)
                       : (lvl == 1) ? (size >= 48.0f && size < 288.0f)
                                    : (size >= 128.0f);
            if (cls == 0.0f && smask) {
                float cxg = cx / s, cyg = cy / s;
                float gtx1 = cx - w * 0.5f, gty1 = cy - h * 0.5f;
                float gtx2 = cx + w * 0.5f, gty2 = cy + h * 0.5f;
                float bxlo = gtx1 / s, bxhi = gtx2 / s, bylo = gty1 / s, byhi = gty2 / s;
                float garea = (gtx2 - gtx1) * (gty2 - gty1);

                int x0 = max(0, (int)floorf(fminf(cxg - 2.5f, bxlo)));
                int x1 = min(Wd - 1, (int)ceilf(fmaxf(cxg + 2.5f, bxhi)));
                int y0 = max(0, (int)floorf(fminf(cyg - 2.5f, bylo)));
                int y1 = min(Wd - 1, (int)ceilf(fmaxf(cyg + 2.5f, byhi)));
                int nx  = x1 - x0 + 1;
                int tot = nx * (y1 - y0 + 1);

                int xi = lane % nx, yi = lane / nx;
                int stepy = 32 / nx, stepx = 32 % nx;
                int niter = (lane < tot) ? ((tot - 1 - lane) >> 5) + 1 : 0;

                ull a[10];
                #pragma unroll
                for (int j = 0; j < 10; ++j) a[j] = ~0ull;
                int cnt = 0; float isum = 0.0f;

                for (int it = 0; it < niter; ++it) {
                    int x = x0 + xi, y = y0 + yi;
                    xi += stepx; yi += stepy;
                    if (xi >= nx) { xi -= nx; yi += 1; }

                    float gx = (float)x, gy = (float)y;
                    bool inc = (fabsf(gx - cxg) < 2.5f) & (fabsf(gy - cyg) < 2.5f);
                    bool inb = (gx >= bxlo) & (gx < bxhi) & (gy >= bylo) & (gy < byhi);
                    if (!(inc | inb)) continue;
                    int cell = y * Wd + x;
                    float iou  = iou_xy(predb, HW, cell, gx, gy, s,
                                        gtx1, gty1, gtx2, gty2, garea);
                    float q0   = __ldg(predb + cell);
                    float cost = fsoftplus(-q0) - 3.0f * __logf(iou + 1e-7f);
                    cnt++; isum += iou;
                    ull key = ((ull)ford(cost) << 32) | (unsigned)cell;
                    if (key < a[9]) {
                        a[9] = key;
                        #pragma unroll
                        for (int j = 8; j >= 0; --j) {
                            ull lo = a[j] < a[j + 1] ? a[j] : a[j + 1];
                            ull hi = a[j] < a[j + 1] ? a[j + 1] : a[j];
                            a[j] = lo; a[j + 1] = hi;
                        }
                    }
                }
                #pragma unroll
                for (int o = 16; o; o >>= 1) {
                    cnt  += __shfl_xor_sync(FULLMASK, cnt, o);
                    isum += __shfl_xor_sync(FULLMASK, isum, o);
                }

                int bc0 = -1;
                #pragma unroll
                for (int t = 0; t < 10; ++t) {
                    ull m = a[0];
                    #pragma unroll
                    for (int o = 16; o; o >>= 1) {
                        ull u = __shfl_xor_sync(FULLMASK, m, o);
                        m = u < m ? u : m;
                    }
                    int cellv = (m == ~0ull) ? -1 : (int)(unsigned)(m & 0xffffffffu);
                    if (t == 0) bc0 = cellv;
                    if (lane == 0) g_sel[gw].idx[t] = cellv;
                    if (a[0] == m && m != ~0ull) {
                        #pragma unroll
                        for (int j = 0; j < 9; ++j) a[j] = a[j + 1];
                        a[9] = ~0ull;
                    }
                }
                if (lane == 0) {
                    if (cnt > 0) {
                        int bx = bc0 % Wd, by = bc0 / Wd;
                        float biou = iou_xy(predb, HW, bc0, (float)bx, (float)by, s,
                                            gtx1, gty1, gtx2, gty2, garea);
                        int hi = cnt < 10 ? cnt : 10;
                        int np = (int)floorf(isum);
                        np = np < 1 ? 1 : np;
                        np = np > hi ? hi : np;
                        SelR& sr = g_sel[gw];
                        sr.np = np;   sr.biou = biou;
                        sr.cxg = cxg; sr.cyg = cyg;
                        sr.twt = __logf(w / s + 1e-7f);
                        sr.tht = __logf(h / s + 1e-7f);
                        sr.f0  = __ldg(T + 5); sr.f1 = __ldg(T + 6);
                    } else {
                        g_sel[gw].np = 0;
                    }
                }
            } else {
                if (lane == 0) g_sel[gw].np = 0;          // invalid GT: no-op
            }
        }

        // ---- group arrival: last of 5 blocks performs apply + loss ----
        __syncthreads();
        if (tid == 0) {
            __threadfence();
            unsigned t = atomicAdd(&g_gcnt[grp], 1u);
            sm.flag = (t == 4u) ? 1 : 0;
        }
        __syncthreads();

        if (sm.flag) {
            if (tid == 0) g_gcnt[grp] = 0;                // reset for next replay
            __threadfence();                              // acquire g_sel writes
            float invHW = 1.0f / (float)HW;

            {
                const int* src = (const int*)&g_sel[grp * 40];
                int*       dst = (int*)sm.sel;
                for (int i = tid; i < 40 * (int)(sizeof(SelR) / 4); i += 256)
                    dst[i] = src[i];
            }
            for (int i = tid; i < HSZ; i += 256) { sm.hkey[i] = -1; sm.hval[i] = -1; }
            __syncthreads();

            // phase A: ownership (owner = max g per cell) via shared hash
            for (int i = tid; i < 400; i += 256) {
                int g2 = i / 10, k = i % 10;
                if (k < sm.sel[g2].np) {
                    int cell = sm.sel[g2].idx[k];
                    int slot = (int)(((unsigned)cell * 2654435761u) >> 22) & HMASK;
                    while (true) {
                        int kk = atomicCAS(&sm.hkey[slot], -1, cell);
                        if (kk == -1 || kk == cell) break;
                        slot = (slot + 1) & HMASK;
                    }
                    atomicMax(&sm.hval[slot], g2);
                }
            }
            __syncthreads();

            // phase B: deterministic entry assignment (tid-ordered ballot)
            int base = 0;
            #pragma unroll
            for (int it = 0; it < 2; ++it) {
                int i = it * 256 + tid;
                int g2 = i / 10, k = i % 10;
                bool act = (i < 400) && (k < sm.sel[g2].np);
                int slot = -1; bool own = false;
                if (act) {
                    int cell = sm.sel[g2].idx[k];
                    slot = (int)(((unsigned)cell * 2654435761u) >> 22) & HMASK;
                    while (sm.hkey[slot] != cell) slot = (slot + 1) & HMASK;
                    own = (sm.hval[slot] == g2);
                }
                unsigned bal = __ballot_sync(FULLMASK, own);
                int wpre = __popc(bal & ((1u << lane) - 1));
                if (lane == 0) sm.wcnt[warp] = __popc(bal);
                __syncthreads();
                if (tid == 0) {
                    int ssum = base;
                    #pragma unroll
                    for (int w2 = 0; w2 < 8; ++w2) { sm.wbase[w2] = ssum; ssum += sm.wcnt[w2]; }
                    sm.nE = ssum;
                }
                __syncthreads();
                if (own) {
                    int e = sm.wbase[warp] + wpre;
                    const SelR& sr = sm.sel[g2];
                    int cell = sr.idx[k];
                    float gxi = (float)(cell % Wd), gyi = (float)(cell / Wd);
                    sm.e_cell[e] = cell;
                    sm.e_obj[e]  = 0u;
                    sm.e_b0[e] = sr.cxg - gxi;
                    sm.e_b1[e] = sr.cyg - gyi;
                    sm.e_b2[e] = sr.twt;
                    sm.e_b3[e] = sr.tht;
                    sm.e_f0[e] = sr.f0;
                    sm.e_f1[e] = sr.f1;
                    sm.hent[slot] = e;
                }
                base = sm.nE;
                __syncthreads();
            }

            // phase C: obj target = max biou over all selecting GTs
            for (int i = tid; i < 400; i += 256) {
                int g2 = i / 10, k = i % 10;
                if (k < sm.sel[g2].np) {
                    int cell = sm.sel[g2].idx[k];
                    int slot = (int)(((unsigned)cell * 2654435761u) >> 22) & HMASK;
                    while (sm.hkey[slot] != cell) slot = (slot + 1) & HMASK;
                    atomicMax(&sm.e_obj[sm.hent[slot]], __float_as_uint(sm.sel[g2].biou));
                }
            }
            __syncthreads();

            // losses over positive cells (obj correction uses LUT base for consistency)
            int nE = sm.nE;
            float npos = fmaxf((float)nE, 1.0f);
            float objc = 0.0f, boxs = 0.0f, fts = 0.0f;
            for (int e = tid; e < nE; e += 256) {
                int cl = sm.e_cell[e];
                float q0 = __ldg(predb + cl);
                float q1 = __ldg(predb + HW + cl);
                float q2 = __ldg(predb + 2 * HW + cl);
                float q3 = __ldg(predb + 3 * HW + cl);
                float q4 = __ldg(predb + 4 * HW + cl);
                float q5 = __ldg(predb + 5 * HW + cl);
                float q6 = __ldg(predb + 6 * HW + cl);

                float z = __uint_as_float(sm.e_obj[e]);
                objc += ffocal(q0, z) - lut0(q0, sm.lut);

                float gx = (float)(cl % Wd), gy = (float)(cl / Wd);
                float pcx = (fsig(q1) + gx) * s;
                float pcy = (fsig(q2) + gy) * s;
                float pw  = __expf(fminf(fmaxf(q3, -5.0f), 5.0f)) * s;
                float ph  = __expf(fminf(fmaxf(q4, -5.0f), 5.0f)) * s;
                float tcx = (sm.e_b0[e] + gx) * s;
                float tcy = (sm.e_b1[e] + gy) * s;
                float tw  = __expf(sm.e_b2[e]) * s;
                float th  = __expf(sm.e_b3[e]) * s;

                float px1 = pcx - pw * 0.5f, py1 = pcy - ph * 0.5f;
                float px2 = pcx + pw * 0.5f, py2 = pcy + ph * 0.5f;
                float tx1 = tcx - tw * 0.5f, ty1 = tcy - th * 0.5f;
                float tx2 = tcx + tw * 0.5f, ty2 = tcy + th * 0.5f;
                float iw    = fmaxf(fminf(px2, tx2) - fmaxf(px1, tx1), 0.0f);
                float ih    = fmaxf(fminf(py2, ty2) - fmaxf(py1, ty1), 0.0f);
                float inter = iw * ih;
                float uni   = pw * ph + tw * th - inter + 1e-7f;
                float iou   = __fdividef(inter, uni);
                float rho2  = (pcx - tcx) * (pcx - tcx) + (pcy - tcy) * (pcy - tcy);
                float cw = fmaxf(px2, tx2) - fminf(px1, tx1);
                float ch = fmaxf(py2, ty2) - fminf(py1, ty1);
                float c2 = cw * cw + ch * ch + 1e-7f;
                float dv = atanf(__fdividef(tw, th + 1e-7f)) - atanf(__fdividef(pw, ph + 1e-7f));
                float v  = 0.40528473456935108577f * dv * dv;  // 4/pi^2
                float alpha = __fdividef(v, 1.0f - iou + v + 1e-7f);
                float ciou  = iou - __fdividef(rho2, c2) - alpha * v;
                boxs += 1.0f - ciou;

                float pf0 = fsig(q5), pf1 = fsig(q6);
                float d0 = fabsf(pf0 - sm.e_f0[e]);
                float d1 = fabsf(pf1 - sm.e_f1[e]);
                fts += (d0 < 1.0f ? 0.5f * d0 * d0 : d0 - 0.5f)
                     + (d1 < 1.0f ? 0.5f * d1 * d1 : d1 - 0.5f);
            }

            float tobj = blk_reduce(objc, sm.red, tid);
            float tbox = blk_reduce(boxs, sm.red, tid);
            float tft  = blk_reduce(fts,  sm.red, tid);
            part = tobj * invHW + 5.0f * tbox / npos + 1.0f * tft / npos;
        }
    }

    // ================= dense chunk stealing (ALL blocks) =================
    {
        const float4* v0 = (const float4*)p0;
        const float4* v1 = (const float4*)p1;
        const float4* v2 = (const float4*)p2;
        for (;;) {
            __syncthreads();
            if (tid == 0) sm.chunkid = (int)atomicAdd(&g_chunk_ctr, 1u);
            __syncthreads();
            int c = sm.chunkid;
            if (c >= NCHUNK) break;
            float acc = dense_chunk(c, tid, sm.lut, v0, v1, v2);
            float t = blk_reduce(acc, sm.red, tid);
            if (tid == 0) g_chunksum[c] = t;
        }
    }

    // ---- arrival counter; last block does the deterministic final sum ----
    if (tid == 0) {
        g_part[blockIdx.x] = part;
        __threadfence();
        unsigned t = atomicAdd(&g_count, 1u);
        sm.flag = (t == GRID_ALL - 1) ? 1 : 0;
    }
    __syncthreads();
    if (sm.flag) {
        __threadfence();
        float acc = 0.0f;
        for (int i = tid; i < GRID_ALL; i += 256) acc += g_part[i];
        for (int i = tid; i < NCHUNK; i += 256) acc += g_chunksum[i];
        float tot = blk_reduce(acc, sm.red, tid);
        if (tid == 0) {
            out[0] = tot / 64.0f;
            g_count = 0;                  // reset for next graph replay
            g_chunk_ctr = 0;
        }
    }
}

// ---------------- host ----------------
extern "C" void kernel_launch(void* const* d_in, const int* in_sizes, int n_in,
                              void* d_out, int out_size)
{
    const float *p0 = nullptr, *p1 = nullptr, *p2 = nullptr, *tg = nullptr;
    for (int i = 0; i < n_in; ++i) {
        int sz = in_sizes[i];
        if      (sz == 64 * 7 * 160 * 160) p0 = (const float*)d_in[i];
        else if (sz == 64 * 7 * 80 * 80)   p1 = (const float*)d_in[i];
        else if (sz == 64 * 7 * 40 * 40)   p2 = (const float*)d_in[i];
        else if (sz == 64 * 40 * 7)        tg = (const float*)d_in[i];
    }

    cudaFuncSetAttribute(k_all, cudaFuncAttributeMaxDynamicSharedMemorySize,
                         (int)sizeof(SmS));

    k_lut<<<LUTN / 256, 256>>>();
    k_all<<<GRID_ALL, 256, sizeof(SmS)>>>(p0, p1, p2, tg, (float*)d_out);
}

// round 13
// speedup vs baseline: 1.2111x; 1.1556x over previous
#include <cuda_runtime.h>
#include <math.h>

typedef unsigned long long ull;
#define FULLMASK 0xffffffffu

#define NSEL_BLK  960               // 192 groups x 5 blocks, 8 warps = 1 GT/warp
#define NDENSE    1024
#define GRID_ALL  (NSEL_BLK + NDENSE)
#define HSZ       1024
#define HMASK     1023

// ---------------- device scratch ----------------
struct SelR {
    int   idx[10];
    int   np;
    float biou, cxg, cyg, twt, tht, f0, f1;
};
__device__ SelR     g_sel[192 * 40];
__device__ unsigned g_gcnt[192];      // per-group arrival counters (self-resetting)
__device__ float    g_part[GRID_ALL];
__device__ unsigned g_count = 0;

struct SmS {
    int      hkey[HSZ], hval[HSZ], hent[HSZ];
    int      e_cell[400];
    unsigned e_obj[400];
    float    e_b0[400], e_b1[400], e_b2[400], e_b3[400], e_f0[400], e_f1[400];
    SelR     sel[40];
    float    red[8];
    int      wcnt[8], wbase[8];
    int      nE;
    int      flag;
};

// ---------------- fast math helpers ----------------
static __device__ __forceinline__ float fsig(float x) {
    return __fdividef(1.0f, 1.0f + __expf(-x));
}
static __device__ __forceinline__ float fsoftplus(float x) {
    return fmaxf(x, 0.0f) + __logf(1.0f + __expf(-fabsf(x)));
}
static __device__ __forceinline__ float ffocal0(float x) {
    float t  = __expf(-fabsf(x));
    float r  = __fdividef(1.0f, 1.0f + t);
    float sg = (x >= 0.0f) ? r : t * r;       // sigmoid(x)
    float ce = fmaxf(x, 0.0f) + __logf(1.0f + t);
    return 0.75f * sg * sg * ce;
}
static __device__ __forceinline__ float ffocal(float x, float z) {
    float t    = __expf(-fabsf(x));
    float r    = __fdividef(1.0f, 1.0f + t);
    float prob = (x >= 0.0f) ? r : t * r;
    float ce   = fmaxf(x, 0.0f) - x * z + __logf(1.0f + t);
    float pt   = prob * z + (1.0f - prob) * (1.0f - z);
    float at   = 0.25f * z + 0.75f * (1.0f - z);
    float om   = 1.0f - pt;
    return at * om * om * ce;
}
static __device__ __forceinline__ unsigned ford(float f) {
    unsigned u = __float_as_uint(f);
    return (u & 0x80000000u) ? ~u : (u | 0x80000000u);
}

static __device__ __forceinline__ float iou_xy(
    const float* __restrict__ predb, int HW, int cell, float gx, float gy, float s,
    float gtx1, float gty1, float gtx2, float gty2, float garea)
{
    float q1 = __ldg(predb + HW + cell);
    float q2 = __ldg(predb + 2 * HW + cell);
    float q3 = __ldg(predb + 3 * HW + cell);
    float q4 = __ldg(predb + 4 * HW + cell);
    float pcx = (fsig(q1) + gx) * s;
    float pcy = (fsig(q2) + gy) * s;
    float pw  = __expf(fminf(fmaxf(q3, -5.0f), 5.0f)) * s;
    float ph  = __expf(fminf(fmaxf(q4, -5.0f), 5.0f)) * s;
    float px1 = pcx - pw * 0.5f, py1 = pcy - ph * 0.5f;
    float px2 = pcx + pw * 0.5f, py2 = pcy + ph * 0.5f;
    float iw    = fmaxf(fminf(px2, gtx2) - fmaxf(px1, gtx1), 0.0f);
    float ih    = fmaxf(fminf(py2, gty2) - fmaxf(py1, gty1), 0.0f);
    float inter = iw * ih;
    float pa    = (px2 - px1) * (py2 - py1);
    return __fdividef(inter, pa + garea - inter + 1e-7f);
}

// deterministic 8-warp block reduction; result valid in warp 0.
static __device__ __forceinline__ float blk_reduce(float v, float* red, int tid) {
    #pragma unroll
    for (int o = 16; o; o >>= 1) v += __shfl_xor_sync(FULLMASK, v, o);
    if ((tid & 31) == 0) red[tid >> 5] = v;
    __syncthreads();
    float r = 0.0f;
    if (tid < 32) {
        r = (tid < 8) ? red[tid] : 0.0f;
        #pragma unroll
        for (int o = 4; o; o >>= 1) r += __shfl_xor_sync(FULLMASK, r, o);
    }
    __syncthreads();
    return r;
}

// level params from group id (grp = lvl*64 + b)
static __device__ __forceinline__ void lvl_params(
    int grp, const float* p0, const float* p1, const float* p2,
    const float*& pred, int& Wd, int& HW, float& s, int& b)
{
    b = grp & 63; int lvl = grp >> 6;
    if (lvl == 0)      { pred = p0; Wd = 160; HW = 25600; s = (float)(8.0  / 1280.0); }
    else if (lvl == 1) { pred = p1; Wd = 80;  HW = 6400;  s = (float)(16.0 / 1280.0); }
    else               { pred = p2; Wd = 40;  HW = 1600;  s = (float)(32.0 / 1280.0); }
}

// ---------------- the single kernel ----------------
// __launch_bounds__(256, 6): cap regs at ~42 so 6 blocks (1536 thr) fit per SM.
__global__ void __launch_bounds__(256, 6)
k_all(const float* __restrict__ p0, const float* __restrict__ p1,
      const float* __restrict__ p2, const float* __restrict__ tgt,
      float* __restrict__ out)
{
    extern __shared__ char smraw[];
    SmS& sm = *reinterpret_cast<SmS*>(smraw);
    int tid = threadIdx.x, lane = tid & 31, warp = tid >> 5;
    float part = 0.0f;

    if (blockIdx.x >= NSEL_BLK) {
        // ================= dense obj focal base (z = 0), float4 =================
        int di = blockIdx.x - NSEL_BLK;              // 0..1023
        const int STRD = NDENSE * 256;
        float acc = 0.0f;
        const float4* v0 = (const float4*)p0;
        const float4* v1 = (const float4*)p1;
        const float4* v2 = (const float4*)p2;
        for (int i = di * 256 + tid; i < 64 * 6400; i += STRD) {
            int b = i / 6400, j = i - b * 6400;
            float4 x = __ldg(v0 + (size_t)b * 7 * 6400 + j);
            acc += (ffocal0(x.x) + ffocal0(x.y) + ffocal0(x.z) + ffocal0(x.w))
                   * (1.0f / 25600.0f);
        }
        for (int i = di * 256 + tid; i < 64 * 1600; i += STRD) {
            int b = i / 1600, j = i - b * 1600;
            float4 x = __ldg(v1 + (size_t)b * 7 * 1600 + j);
            acc += (ffocal0(x.x) + ffocal0(x.y) + ffocal0(x.z) + ffocal0(x.w))
                   * (1.0f / 6400.0f);
        }
        for (int i = di * 256 + tid; i < 64 * 400; i += STRD) {
            int b = i / 400, j = i - b * 400;
            float4 x = __ldg(v2 + (size_t)b * 7 * 400 + j);
            acc += (ffocal0(x.x) + ffocal0(x.y) + ffocal0(x.z) + ffocal0(x.w))
                   * (1.0f / 1600.0f);
        }
        part = blk_reduce(acc, sm.red, tid);
    } else {
        // ================= selection: one warp per GT =================
        int grp = blockIdx.x / 5, sub = blockIdx.x % 5;   // grp = lvl*64 + b
        const float* pred; int Wd, HW, b; float s;
        lvl_params(grp, p0, p1, p2, pred, Wd, HW, s, b);
        int lvl = grp >> 6;
        const float* predb = pred + (size_t)b * 7 * HW;

        int g  = sub * 8 + warp;                          // this warp's GT, 0..39
        int gw = grp * 40 + g;
        {
            const float* T = tgt + (size_t)(b * 40 + g) * 7;
            float cls = __ldg(T + 0), cx = __ldg(T + 1), cy = __ldg(T + 2);
            float w   = __ldg(T + 3), h  = __ldg(T + 4);
            float size = fmaxf(w, h) * 1280.0f;
            bool smask = (lvl == 0) ? (size < 128.0f)
                       : (lvl == 1) ? (size >= 48.0f && size < 288.0f)
                                    : (size >= 128.0f);
            if (cls == 0.0f && smask) {
                float cxg = cx / s, cyg = cy / s;
                float gtx1 = cx - w * 0.5f, gty1 = cy - h * 0.5f;
                float gtx2 = cx + w * 0.5f, gty2 = cy + h * 0.5f;
                float bxlo = gtx1 / s, bxhi = gtx2 / s, bylo = gty1 / s, byhi = gty2 / s;
                float garea = (gtx2 - gtx1) * (gty2 - gty1);

                int x0 = max(0, (int)floorf(fminf(cxg - 2.5f, bxlo)));
                int x1 = min(Wd - 1, (int)ceilf(fmaxf(cxg + 2.5f, bxhi)));
                int y0 = max(0, (int)floorf(fminf(cyg - 2.5f, bylo)));
                int y1 = min(Wd - 1, (int)ceilf(fmaxf(cyg + 2.5f, byhi)));
                int nx  = x1 - x0 + 1;
                int tot = nx * (y1 - y0 + 1);

                int xi = lane % nx, yi = lane / nx;
                int stepy = 32 / nx, stepx = 32 % nx;
                int niter = (lane < tot) ? ((tot - 1 - lane) >> 5) + 1 : 0;

                ull a[10];
                #pragma unroll
                for (int j = 0; j < 10; ++j) a[j] = ~0ull;
                int cnt = 0; float isum = 0.0f;

                for (int it = 0; it < niter; ++it) {
                    int x = x0 + xi, y = y0 + yi;
                    xi += stepx; yi += stepy;
                    if (xi >= nx) { xi -= nx; yi += 1; }

                    float gx = (float)x, gy = (float)y;
                    bool inc = (fabsf(gx - cxg) < 2.5f) & (fabsf(gy - cyg) < 2.5f);
                    bool inb = (gx >= bxlo) & (gx < bxhi) & (gy >= bylo) & (gy < byhi);
                    if (!(inc | inb)) continue;
                    int cell = y * Wd + x;
                    float iou  = iou_xy(predb, HW, cell, gx, gy, s,
                                        gtx1, gty1, gtx2, gty2, garea);
                    float q0   = __ldg(predb + cell);
                    float cost = fsoftplus(-q0) - 3.0f * __logf(iou + 1e-7f);
                    cnt++; isum += iou;
                    ull key = ((ull)ford(cost) << 32) | (unsigned)cell;
                    if (key < a[9]) {
                        a[9] = key;
                        #pragma unroll
                        for (int j = 8; j >= 0; --j) {
                            ull lo = a[j] < a[j + 1] ? a[j] : a[j + 1];
                            ull hi = a[j] < a[j + 1] ? a[j + 1] : a[j];
                            a[j] = lo; a[j + 1] = hi;
                        }
                    }
                }
                #pragma unroll
                for (int o = 16; o; o >>= 1) {
                    cnt  += __shfl_xor_sync(FULLMASK, cnt, o);
                    isum += __shfl_xor_sync(FULLMASK, isum, o);
                }

                int bc0 = -1;
                #pragma unroll
                for (int t = 0; t < 10; ++t) {
                    ull m = a[0];
                    #pragma unroll
                    for (int o = 16; o; o >>= 1) {
                        ull u = __shfl_xor_sync(FULLMASK, m, o);
                        m = u < m ? u : m;
                    }
                    int cellv = (m == ~0ull) ? -1 : (int)(unsigned)(m & 0xffffffffu);
                    if (t == 0) bc0 = cellv;
                    if (lane == 0) g_sel[gw].idx[t] = cellv;
                    if (a[0] == m && m != ~0ull) {
                        #pragma unroll
                        for (int j = 0; j < 9; ++j) a[j] = a[j + 1];
                        a[9] = ~0ull;
                    }
                }
                if (lane == 0) {
                    if (cnt > 0) {
                        int bx = bc0 % Wd, by = bc0 / Wd;
                        float biou = iou_xy(predb, HW, bc0, (float)bx, (float)by, s,
                                            gtx1, gty1, gtx2, gty2, garea);
                        int hi = cnt < 10 ? cnt : 10;
                        int np = (int)floorf(isum);
                        np = np < 1 ? 1 : np;
                        np = np > hi ? hi : np;
                        SelR& sr = g_sel[gw];
                        sr.np = np;   sr.biou = biou;
                        sr.cxg = cxg; sr.cyg = cyg;
                        sr.twt = __logf(w / s + 1e-7f);
                        sr.tht = __logf(h / s + 1e-7f);
                        sr.f0  = __ldg(T + 5); sr.f1 = __ldg(T + 6);
                    } else {
                        g_sel[gw].np = 0;
                    }
                }
            } else {
                if (lane == 0) g_sel[gw].np = 0;          // invalid GT: no-op
            }
        }

        // ---- group arrival: last of 5 blocks performs apply + loss ----
        __syncthreads();
        if (tid == 0) {
            __threadfence();
            unsigned t = atomicAdd(&g_gcnt[grp], 1u);
            sm.flag = (t == 4u) ? 1 : 0;
        }
        __syncthreads();

        if (sm.flag) {
            if (tid == 0) g_gcnt[grp] = 0;               // reset for next replay
            __threadfence();                              // acquire g_sel writes
            float invHW = 1.0f / (float)HW;

            {
                const int* src = (const int*)&g_sel[grp * 40];
                int*       dst = (int*)sm.sel;
                for (int i = tid; i < 40 * (int)(sizeof(SelR) / 4); i += 256)
                    dst[i] = src[i];
            }
            for (int i = tid; i < HSZ; i += 256) { sm.hkey[i] = -1; sm.hval[i] = -1; }
            __syncthreads();

            // phase A: ownership (owner = max g per cell) via shared hash
            for (int i = tid; i < 400; i += 256) {
                int g2 = i / 10, k = i % 10;
                if (k < sm.sel[g2].np) {
                    int cell = sm.sel[g2].idx[k];
                    int slot = (int)(((unsigned)cell * 2654435761u) >> 22) & HMASK;
                    while (true) {
                        int kk = atomicCAS(&sm.hkey[slot], -1, cell);
                        if (kk == -1 || kk == cell) break;
                        slot = (slot + 1) & HMASK;
                    }
                    atomicMax(&sm.hval[slot], g2);
                }
            }
            __syncthreads();

            // phase B: deterministic entry assignment (tid-ordered ballot)
            int base = 0;
            #pragma unroll
            for (int it = 0; it < 2; ++it) {
                int i = it * 256 + tid;
                int g2 = i / 10, k = i % 10;
                bool act = (i < 400) && (k < sm.sel[g2].np);
                int slot = -1; bool own = false;
                if (act) {
                    int cell = sm.sel[g2].idx[k];
                    slot = (int)(((unsigned)cell * 2654435761u) >> 22) & HMASK;
                    while (sm.hkey[slot] != cell) slot = (slot + 1) & HMASK;
                    own = (sm.hval[slot] == g2);
                }
                unsigned bal = __ballot_sync(FULLMASK, own);
                int wpre = __popc(bal & ((1u << lane) - 1));
                if (lane == 0) sm.wcnt[warp] = __popc(bal);
                __syncthreads();
                if (tid == 0) {
                    int ssum = base;
                    #pragma unroll
                    for (int w2 = 0; w2 < 8; ++w2) { sm.wbase[w2] = ssum; ssum += sm.wcnt[w2]; }
                    sm.nE = ssum;
                }
                __syncthreads();
                if (own) {
                    int e = sm.wbase[warp] + wpre;
                    const SelR& sr = sm.sel[g2];
                    int cell = sr.idx[k];
                    float gxi = (float)(cell % Wd), gyi = (float)(cell / Wd);
                    sm.e_cell[e] = cell;
                    sm.e_obj[e]  = 0u;
                    sm.e_b0[e] = sr.cxg - gxi;
                    sm.e_b1[e] = sr.cyg - gyi;
                    sm.e_b2[e] = sr.twt;
                    sm.e_b3[e] = sr.tht;
                    sm.e_f0[e] = sr.f0;
                    sm.e_f1[e] = sr.f1;
                    sm.hent[slot] = e;
                }
                base = sm.nE;
                __syncthreads();
            }

            // phase C: obj target = max biou over all selecting GTs
            for (int i = tid; i < 400; i += 256) {
                int g2 = i / 10, k = i % 10;
                if (k < sm.sel[g2].np) {
                    int cell = sm.sel[g2].idx[k];
                    int slot = (int)(((unsigned)cell * 2654435761u) >> 22) & HMASK;
                    while (sm.hkey[slot] != cell) slot = (slot + 1) & HMASK;
                    atomicMax(&sm.e_obj[sm.hent[slot]], __float_as_uint(sm.sel[g2].biou));
                }
            }
            __syncthreads();

            // losses over positive cells
            int nE = sm.nE;
            float npos = fmaxf((float)nE, 1.0f);
            float objc = 0.0f, boxs = 0.0f, fts = 0.0f;
            for (int e = tid; e < nE; e += 256) {
                int cl = sm.e_cell[e];
                float q0 = __ldg(predb + cl);
                float q1 = __ldg(predb + HW + cl);
                float q2 = __ldg(predb + 2 * HW + cl);
                float q3 = __ldg(predb + 3 * HW + cl);
                float q4 = __ldg(predb + 4 * HW + cl);
                float q5 = __ldg(predb + 5 * HW + cl);
                float q6 = __ldg(predb + 6 * HW + cl);

                float z = __uint_as_float(sm.e_obj[e]);
                objc += ffocal(q0, z) - ffocal0(q0);

                float gx = (float)(cl % Wd), gy = (float)(cl / Wd);
                float pcx = (fsig(q1) + gx) * s;
                float pcy = (fsig(q2) + gy) * s;
                float pw  = __expf(fminf(fmaxf(q3, -5.0f), 5.0f)) * s;
                float ph  = __expf(fminf(fmaxf(q4, -5.0f), 5.0f)) * s;
                float tcx = (sm.e_b0[e] + gx) * s;
                float tcy = (sm.e_b1[e] + gy) * s;
                float tw  = __expf(sm.e_b2[e]) * s;
                float th  = __expf(sm.e_b3[e]) * s;

                float px1 = pcx - pw * 0.5f, py1 = pcy - ph * 0.5f;
                float px2 = pcx + pw * 0.5f, py2 = pcy + ph * 0.5f;
                float tx1 = tcx - tw * 0.5f, ty1 = tcy - th * 0.5f;
                float tx2 = tcx + tw * 0.5f, ty2 = tcy + th * 0.5f;
                float iw    = fmaxf(fminf(px2, tx2) - fmaxf(px1, tx1), 0.0f);
                float ih    = fmaxf(fminf(py2, ty2) - fmaxf(py1, ty1), 0.0f);
                float inter = iw * ih;
                float uni   = pw * ph + tw * th - inter + 1e-7f;
                float iou   = __fdividef(inter, uni);
                float rho2  = (pcx - tcx) * (pcx - tcx) + (pcy - tcy) * (pcy - tcy);
                float cw = fmaxf(px2, tx2) - fminf(px1, tx1);
                float ch = fmaxf(py2, ty2) - fminf(py1, ty1);
                float c2 = cw * cw + ch * ch + 1e-7f;
                float dv = atanf(__fdividef(tw, th + 1e-7f)) - atanf(__fdividef(pw, ph + 1e-7f));
                float v  = 0.40528473456935108577f * dv * dv;  // 4/pi^2
                float alpha = __fdividef(v, 1.0f - iou + v + 1e-7f);
                float ciou  = iou - __fdividef(rho2, c2) - alpha * v;
                boxs += 1.0f - ciou;

                float pf0 = fsig(q5), pf1 = fsig(q6);
                float d0 = fabsf(pf0 - sm.e_f0[e]);
                float d1 = fabsf(pf1 - sm.e_f1[e]);
                fts += (d0 < 1.0f ? 0.5f * d0 * d0 : d0 - 0.5f)
                     + (d1 < 1.0f ? 0.5f * d1 * d1 : d1 - 0.5f);
            }

            float tobj = blk_reduce(objc, sm.red, tid);
            float tbox = blk_reduce(boxs, sm.red, tid);
            float tft  = blk_reduce(fts,  sm.red, tid);
            part = tobj * invHW + 5.0f * tbox / npos + 1.0f * tft / npos;
        }
    }

    // ---- arrival counter; last block does the deterministic final sum ----
    __syncthreads();
    if (tid == 0) {
        g_part[blockIdx.x] = part;
        __threadfence();
        unsigned t = atomicAdd(&g_count, 1u);
        sm.flag = (t == GRID_ALL - 1) ? 1 : 0;
    }
    __syncthreads();
    if (sm.flag) {
        __threadfence();
        float acc = 0.0f;
        for (int i = tid; i < GRID_ALL; i += 256) acc += g_part[i];
        float tot = blk_reduce(acc, sm.red, tid);
        if (tid == 0) {
            out[0] = tot / 64.0f;
            g_count = 0;                  // reset for next graph replay
        }
    }
}

// ---------------- host ----------------
extern "C" void kernel_launch(void* const* d_in, const int* in_sizes, int n_in,
                              void* d_out, int out_size)
{
    const float *p0 = nullptr, *p1 = nullptr, *p2 = nullptr, *tg = nullptr;
    for (int i = 0; i < n_in; ++i) {
        int sz = in_sizes[i];
        if      (sz == 64 * 7 * 160 * 160) p0 = (const float*)d_in[i];
        else if (sz == 64 * 7 * 80 * 80)   p1 = (const float*)d_in[i];
        else if (sz == 64 * 7 * 40 * 40)   p2 = (const float*)d_in[i];
        else if (sz == 64 * 40 * 7)        tg = (const float*)d_in[i];
    }

    cudaFuncSetAttribute(k_all, cudaFuncAttributeMaxDynamicSharedMemorySize,
                         (int)sizeof(SmS));

    k_all<<<GRID_ALL, 256, sizeof(SmS)>>>(p0, p1, p2, tg, (float*)d_out);
}